// round 4
// baseline (speedup 1.0000x reference)
#include <cuda_runtime.h>
#include <cuda_bf16.h>
#include <stdint.h>

// Problem constants
#define NR 4096
#define DIM 1024                     // also bytes/row in int8
#define NBLK 272                     // 128x256 tiles covering j>=i
#define STAGE_BYTES 49152            // A: 128x128B (16KB) + B: 256x128B (32KB)
#define SMEM_TOTAL (2 * STAGE_BYTES) // 96KB double buffer

// Scratch (static device globals; no runtime allocation)
__device__ int8_t g_zq[NR * DIM];    // normalized z1 * 256, int8 (4 MB, L2-resident)
__device__ float g_sq[NR];
__device__ float g_pos[NR];
__device__ float g_negpart[NBLK];

__device__ __forceinline__ uint32_t su32(const void* p) {
    return (uint32_t)__cvta_generic_to_shared(p);
}
__device__ __forceinline__ void cpasync16(uint32_t dst, const void* g) {
    asm volatile("cp.async.cg.shared.global [%0], [%1], 16;" :: "r"(dst), "l"(g));
}
#define CP_COMMIT() asm volatile("cp.async.commit_group;")
#define CP_WAIT(n)  asm volatile("cp.async.wait_group %0;" :: "n"(n))

#define LDMX4(R, addr) \
    asm volatile("ldmatrix.sync.aligned.m8n8.x4.shared.b16 {%0,%1,%2,%3}, [%4];" \
                 : "=r"((R)[0]), "=r"((R)[1]), "=r"((R)[2]), "=r"((R)[3]) : "r"(addr))

__device__ __forceinline__ void imma16832(int* c, const uint32_t* a, const uint32_t* b) {
    asm volatile(
        "mma.sync.aligned.m16n8k32.row.col.s32.s8.s8.s32 "
        "{%0,%1,%2,%3}, {%4,%5,%6,%7}, {%8,%9}, {%0,%1,%2,%3};"
        : "+r"(c[0]), "+r"(c[1]), "+r"(c[2]), "+r"(c[3])
        : "r"(a[0]), "r"(a[1]), "r"(a[2]), "r"(a[3]), "r"(b[0]), "r"(b[1]));
}

__device__ __forceinline__ int q8(float v) {
    int i = __float2int_rn(v);
    return max(-127, min(127, i));
}

// -------------------------------------------------------------------------
// Kernel 1: warp-per-row-pair normalize. Emits int8 (z_normalized * 256).
// Uses dot-product identity for d_pos so z2 is never kept in registers.
// -------------------------------------------------------------------------
__global__ __launch_bounds__(256) void normalize_kernel(const float* __restrict__ z) {
    int warp = threadIdx.x >> 5, lane = threadIdx.x & 31;
    int row = blockIdx.x * 8 + warp;

    const float4* z1p = (const float4*)(z + (size_t)row * DIM);
    const float4* z2p = (const float4*)(z + (size_t)(row + NR) * DIM);

    float4 a[8];
    float s1 = 0.f, s2 = 0.f, s12 = 0.f;
    #pragma unroll
    for (int i = 0; i < 8; i++) {
        a[i] = z1p[lane + 32 * i];
        float4 b = z2p[lane + 32 * i];
        s1  += a[i].x * a[i].x + a[i].y * a[i].y + a[i].z * a[i].z + a[i].w * a[i].w;
        s2  += b.x * b.x + b.y * b.y + b.z * b.z + b.w * b.w;
        s12 += a[i].x * b.x + a[i].y * b.y + a[i].z * b.z + a[i].w * b.w;
    }
    #pragma unroll
    for (int o = 16; o; o >>= 1) {
        s1  += __shfl_xor_sync(0xFFFFFFFFu, s1, o);
        s2  += __shfl_xor_sync(0xFFFFFFFFu, s2, o);
        s12 += __shfl_xor_sync(0xFFFFFFFFu, s12, o);
    }
    float inv1 = 1.f / fmaxf(sqrtf(s1), 1e-12f);
    float inv2 = 1.f / fmaxf(sqrtf(s2), 1e-12f);
    float q1 = 256.f * inv1;     // int8 quantization scale folded in

    uint32_t* dst = (uint32_t*)(g_zq + (size_t)row * DIM);
    #pragma unroll
    for (int i = 0; i < 8; i++) {
        int v0 = q8(a[i].x * q1), v1 = q8(a[i].y * q1);
        int v2 = q8(a[i].z * q1), v3 = q8(a[i].w * q1);
        dst[lane + 32 * i] = (uint32_t)(v0 & 0xFF) | ((uint32_t)(v1 & 0xFF) << 8) |
                             ((uint32_t)(v2 & 0xFF) << 16) | ((uint32_t)(v3 & 0xFF) << 24);
    }
    if (lane == 0) {
        float n1sq = s1 * inv1 * inv1;            // |z1n|^2 (==1 unless clamped)
        float n2sq = s2 * inv2 * inv2;
        float dp = n1sq + n2sq - 2.f * s12 * inv1 * inv2;
        g_pos[row] = logf(__expf(-0.5f * dp) + 1e-8f) + 1.f;
        g_sq[row] = n1sq;
    }
}

// -------------------------------------------------------------------------
// Kernel 2: int8 Gram (mma.sync m16n8k32 s8s8s32) + fused exp-reduce.
// 272 CTAs x 256 threads. CTA tile 128(M) x 256(N); warp tile 64x64.
// 8 K-stages of 128B, double-buffered cp.async, SW128 conflict-free.
// -------------------------------------------------------------------------
__global__ __launch_bounds__(256, 1) void gram_kernel() {
    extern __shared__ uint8_t dsm[];
    uint32_t smem_base = su32(dsm);
    int tid = threadIdx.x;
    int warp = tid >> 5, lane = tid & 31;
    int wr = warp >> 2, wc = warp & 3;   // warp grid 2 x 4

    // bid -> (ti, cs)
    int ti = 0, rem = blockIdx.x;
    #pragma unroll 1
    while (true) { int n = 16 - (ti >> 1); if (rem < n) break; rem -= n; ti++; }
    int cs = ((ti >> 1) + rem) * 256;

    const int8_t* Abase = g_zq + (size_t)ti * 128 * DIM;
    const int8_t* Bbase = g_zq + (size_t)cs * DIM;

    int acc[4][8][4];
    #pragma unroll
    for (int i = 0; i < 4; i++)
        #pragma unroll
        for (int j = 0; j < 8; j++)
            #pragma unroll
            for (int e = 0; e < 4; e++) acc[i][j][e] = 0;

    // stage s covers K bytes [s*128, s*128+128)
    #define LOAD_STAGE(s, slot)                                                   \
        do {                                                                      \
            uint32_t base_ = smem_base + (slot) * STAGE_BYTES;                    \
            const int8_t* Ak = Abase + (s) * 128;                                 \
            const int8_t* Bk = Bbase + (s) * 128;                                 \
            _Pragma("unroll")                                                     \
            for (int x = tid; x < 1024; x += 256) {                               \
                int r_ = x >> 3, c_ = x & 7;                                      \
                uint32_t off = (uint32_t)(r_ * 128 + c_ * 16);                    \
                off ^= (off >> 3) & 0x70;                                         \
                cpasync16(base_ + off, Ak + (size_t)r_ * DIM + c_ * 16);          \
            }                                                                     \
            _Pragma("unroll")                                                     \
            for (int x = tid; x < 2048; x += 256) {                               \
                int r_ = x >> 3, c_ = x & 7;                                      \
                uint32_t off = (uint32_t)(r_ * 128 + c_ * 16);                    \
                off ^= (off >> 3) & 0x70;                                         \
                cpasync16(base_ + 16384 + off, Bk + (size_t)r_ * DIM + c_ * 16);  \
            }                                                                     \
            CP_COMMIT();                                                          \
        } while (0)

    LOAD_STAGE(0, 0);
    LOAD_STAGE(1, 1);

    #pragma unroll 1
    for (int s = 0; s < 8; s++) {
        int slot = s & 1;
        if (s < 7) CP_WAIT(1); else CP_WAIT(0);
        __syncthreads();

        uint32_t sa = smem_base + slot * STAGE_BYTES;
        uint32_t sb = sa + 16384;

        #pragma unroll
        for (int kk = 0; kk < 4; kk++) {
            uint32_t af[4][4];
            #pragma unroll
            for (int mi = 0; mi < 4; mi++) {
                int r = wr * 64 + mi * 16 + (lane & 7) + ((lane >> 3) & 1) * 8;
                int cb = kk * 32 + ((lane >> 4) & 1) * 16;
                uint32_t off = (uint32_t)(r * 128 + cb);
                off ^= (off >> 3) & 0x70;
                LDMX4(af[mi], sa + off);
            }
            uint32_t bf[8][2];
            #pragma unroll
            for (int p = 0; p < 4; p++) {
                int r = wc * 64 + p * 16 + ((lane >> 4) & 1) * 8 + (lane & 7);
                int cb = kk * 32 + ((lane >> 3) & 1) * 16;
                uint32_t off = (uint32_t)(r * 128 + cb);
                off ^= (off >> 3) & 0x70;
                uint32_t t[4];
                LDMX4(t, sb + off);
                bf[2 * p + 0][0] = t[0]; bf[2 * p + 0][1] = t[1];
                bf[2 * p + 1][0] = t[2]; bf[2 * p + 1][1] = t[3];
            }
            #pragma unroll
            for (int mi = 0; mi < 4; mi++)
                #pragma unroll
                for (int ni = 0; ni < 8; ni++)
                    imma16832(acc[mi][ni], af[mi], bf[ni]);
        }

        if (s + 2 < 8) {
            __syncthreads();
            LOAD_STAGE(s + 2, slot);
        }
    }
    __syncthreads();   // buffers dead; reuse smem for sq staging

    float* sqi_sh = (float*)dsm;          // 128 floats
    float* sqj_sh = (float*)dsm + 128;    // 256 floats
    if (tid < 128) sqi_sh[tid] = g_sq[ti * 128 + tid];
    sqj_sh[tid] = g_sq[cs + tid];
    __syncthreads();

    // epilogue: acc holds 65536 * dot. 2*dot = acc / 32768.
    float local = 0.f;
    int r0 = lane >> 2, c0 = (lane & 3) * 2;
    #pragma unroll
    for (int mi = 0; mi < 4; mi++) {
        float si0 = sqi_sh[wr * 64 + mi * 16 + r0];
        float si1 = sqi_sh[wr * 64 + mi * 16 + r0 + 8];
        int gi0 = ti * 128 + wr * 64 + mi * 16 + r0;
        #pragma unroll
        for (int ni = 0; ni < 8; ni++) {
            int jl = wc * 64 + ni * 8 + c0;
            float sj0 = sqj_sh[jl], sj1 = sqj_sh[jl + 1];
            int gj0 = cs + jl;
            #pragma unroll
            for (int e = 0; e < 4; e++) {
                float si = (e >> 1) ? si1 : si0;
                float sj = (e & 1) ? sj1 : sj0;
                int gi = gi0 + ((e >> 1) ? 8 : 0);
                int gj = gj0 + (e & 1);
                float d2 = fmaxf(si + sj - (float)acc[mi][ni][e] * (1.f / 32768.f), 0.f);
                if (gj > gi) local += 2.f * __expf(-0.5f * d2);
            }
        }
    }

    #pragma unroll
    for (int o = 16; o; o >>= 1) local += __shfl_xor_sync(0xFFFFFFFFu, local, o);
    __shared__ float part[8];
    if (lane == 0) part[warp] = local;
    __syncthreads();
    if (tid == 0) {
        float tot = 0.f;
        #pragma unroll
        for (int i = 0; i < 8; i++) tot += part[i];
        g_negpart[blockIdx.x] = tot;
    }
}

// -------------------------------------------------------------------------
// Kernel 3: deterministic finalize
// -------------------------------------------------------------------------
__global__ __launch_bounds__(256) void finalize_kernel(float* out) {
    __shared__ double sh[256];
    int tid = threadIdx.x;

    double p = 0.0;
    for (int i = tid; i < NR; i += 256) p += (double)g_pos[i];
    sh[tid] = p;
    __syncthreads();
    for (int s = 128; s; s >>= 1) {
        if (tid < s) sh[tid] += sh[tid + s];
        __syncthreads();
    }
    double pos_sum = sh[0];
    __syncthreads();

    double n = 0.0;
    for (int i = tid; i < NBLK; i += 256) n += (double)g_negpart[i];
    sh[tid] = n;
    __syncthreads();
    for (int s = 128; s; s >>= 1) {
        if (tid < s) sh[tid] += sh[tid + s];
        __syncthreads();
    }
    if (tid == 0) {
        double star_mean = sh[0] / ((double)NR * (double)(NR - 1)) + 1e-8;
        double loss = -(pos_sum / (double)NR) + 64.0 * star_mean;
        out[0] = (float)loss;
    }
}

extern "C" void kernel_launch(void* const* d_in, const int* in_sizes, int n_in,
                              void* d_out, int out_size) {
    const float* z = (const float*)d_in[0];
    float* out = (float*)d_out;
    static int configured = 0;
    if (!configured) {
        cudaFuncSetAttribute(gram_kernel, cudaFuncAttributeMaxDynamicSharedMemorySize,
                             SMEM_TOTAL);
        configured = 1;
    }
    normalize_kernel<<<512, 256>>>(z);
    gram_kernel<<<NBLK, 256, SMEM_TOTAL>>>();
    finalize_kernel<<<1, 256>>>(out);
}

// round 5
// speedup vs baseline: 2.0510x; 2.0510x over previous
#include <cuda_runtime.h>
#include <cuda_bf16.h>
#include <cuda_fp16.h>
#include <stdint.h>

// Problem constants
#define NR 4096
#define DIM 1024                     // also bytes/row in fp8
#define NBLK 272                     // 128x256 tiles covering j>=i
#define STAGE_BYTES 49152            // A: 128x128B (16KB) + B: 256x128B (32KB)
#define SMEM_TOTAL (2 * STAGE_BYTES) // 96KB double buffer

// Scratch (static device globals; no runtime allocation)
__device__ uint8_t g_zq[NR * DIM];   // normalized z1 * 16, e4m3 (4 MB, L2-resident)
__device__ float g_sq[NR];
__device__ float g_pos[NR];
__device__ float g_negpart[NBLK];

__device__ __forceinline__ uint32_t su32(const void* p) {
    return (uint32_t)__cvta_generic_to_shared(p);
}
__device__ __forceinline__ void cpasync16(uint32_t dst, const void* g) {
    asm volatile("cp.async.cg.shared.global [%0], [%1], 16;" :: "r"(dst), "l"(g));
}
#define CP_COMMIT() asm volatile("cp.async.commit_group;")
#define CP_WAIT(n)  asm volatile("cp.async.wait_group %0;" :: "n"(n))

#define LDMX4(R, addr) \
    asm volatile("ldmatrix.sync.aligned.m8n8.x4.shared.b16 {%0,%1,%2,%3}, [%4];" \
                 : "=r"((R)[0]), "=r"((R)[1]), "=r"((R)[2]), "=r"((R)[3]) : "r"(addr))

// fp8 MMA with f16 accumulator (2 packed regs)
__device__ __forceinline__ void mma16832h(uint32_t* c, const uint32_t* a, const uint32_t* b) {
    asm volatile(
        "mma.sync.aligned.m16n8k32.row.col.f16.e4m3.e4m3.f16 "
        "{%0,%1}, {%2,%3,%4,%5}, {%6,%7}, {%0,%1};"
        : "+r"(c[0]), "+r"(c[1])
        : "r"(a[0]), "r"(a[1]), "r"(a[2]), "r"(a[3]), "r"(b[0]), "r"(b[1]));
}

__device__ __forceinline__ uint32_t pack4_e4m3(float v0, float v1, float v2, float v3) {
    uint16_t h01, h23;
    asm("cvt.rn.satfinite.e4m3x2.f32 %0, %1, %2;" : "=h"(h01) : "f"(v1), "f"(v0));
    asm("cvt.rn.satfinite.e4m3x2.f32 %0, %1, %2;" : "=h"(h23) : "f"(v3), "f"(v2));
    return (uint32_t)h01 | ((uint32_t)h23 << 16);
}

// -------------------------------------------------------------------------
// Kernel 1: warp-per-row-pair normalize. 1024 blocks x 128 thr (4 warps)
// for higher effective occupancy. Emits e4m3 (z * 16).
// -------------------------------------------------------------------------
__global__ __launch_bounds__(128) void normalize_kernel(const float* __restrict__ z) {
    int warp = threadIdx.x >> 5, lane = threadIdx.x & 31;
    int row = blockIdx.x * 4 + warp;

    const float4* z1p = (const float4*)(z + (size_t)row * DIM);
    const float4* z2p = (const float4*)(z + (size_t)(row + NR) * DIM);

    float4 a[8];
    float s1 = 0.f, s2 = 0.f, s12 = 0.f;
    #pragma unroll
    for (int i = 0; i < 8; i++) {
        a[i] = z1p[lane + 32 * i];
        float4 b = z2p[lane + 32 * i];
        s1  += a[i].x * a[i].x + a[i].y * a[i].y + a[i].z * a[i].z + a[i].w * a[i].w;
        s2  += b.x * b.x + b.y * b.y + b.z * b.z + b.w * b.w;
        s12 += a[i].x * b.x + a[i].y * b.y + a[i].z * b.z + a[i].w * b.w;
    }
    #pragma unroll
    for (int o = 16; o; o >>= 1) {
        s1  += __shfl_xor_sync(0xFFFFFFFFu, s1, o);
        s2  += __shfl_xor_sync(0xFFFFFFFFu, s2, o);
        s12 += __shfl_xor_sync(0xFFFFFFFFu, s12, o);
    }
    float inv1 = 1.f / fmaxf(sqrtf(s1), 1e-12f);
    float inv2 = 1.f / fmaxf(sqrtf(s2), 1e-12f);
    float q1 = 16.f * inv1;     // quantization scale folded in

    uint32_t* dst = (uint32_t*)(g_zq + (size_t)row * DIM);
    #pragma unroll
    for (int i = 0; i < 8; i++) {
        dst[lane + 32 * i] = pack4_e4m3(a[i].x * q1, a[i].y * q1, a[i].z * q1, a[i].w * q1);
    }
    if (lane == 0) {
        float n1sq = s1 * inv1 * inv1;            // |z1n|^2 (==1 unless clamped)
        float n2sq = s2 * inv2 * inv2;
        float dp = n1sq + n2sq - 2.f * s12 * inv1 * inv2;
        g_pos[row] = logf(__expf(-0.5f * dp) + 1e-8f) + 1.f;
        g_sq[row] = n1sq;
    }
}

// -------------------------------------------------------------------------
// Kernel 2: fp8 Gram (mma.sync m16n8k32 e4m3, f16 accumulator) + fused
// exp-reduce epilogue. 272 CTAs x 256 threads. CTA tile 128x256; warp 64x64.
// 8 K-stages of 128B, double-buffered cp.async, SW128 conflict-free.
// -------------------------------------------------------------------------
__global__ __launch_bounds__(256, 1) void gram_kernel() {
    extern __shared__ uint8_t dsm[];
    uint32_t smem_base = su32(dsm);
    int tid = threadIdx.x;
    int warp = tid >> 5, lane = tid & 31;
    int wr = warp >> 2, wc = warp & 3;   // warp grid 2 x 4

    // bid -> (ti, cs)
    int ti = 0, rem = blockIdx.x;
    #pragma unroll 1
    while (true) { int n = 16 - (ti >> 1); if (rem < n) break; rem -= n; ti++; }
    int cs = ((ti >> 1) + rem) * 256;

    const uint8_t* Abase = g_zq + (size_t)ti * 128 * DIM;
    const uint8_t* Bbase = g_zq + (size_t)cs * DIM;

    uint32_t acc[4][8][2];   // f16x2 accumulators
    #pragma unroll
    for (int i = 0; i < 4; i++)
        #pragma unroll
        for (int j = 0; j < 8; j++) { acc[i][j][0] = 0u; acc[i][j][1] = 0u; }

    // stage s covers K bytes [s*128, s*128+128)
    #define LOAD_STAGE(s, slot)                                                   \
        do {                                                                      \
            uint32_t base_ = smem_base + (slot) * STAGE_BYTES;                    \
            const uint8_t* Ak = Abase + (s) * 128;                                \
            const uint8_t* Bk = Bbase + (s) * 128;                                \
            _Pragma("unroll")                                                     \
            for (int x = tid; x < 1024; x += 256) {                               \
                int r_ = x >> 3, c_ = x & 7;                                      \
                uint32_t off = (uint32_t)(r_ * 128 + c_ * 16);                    \
                off ^= (off >> 3) & 0x70;                                         \
                cpasync16(base_ + off, Ak + (size_t)r_ * DIM + c_ * 16);          \
            }                                                                     \
            _Pragma("unroll")                                                     \
            for (int x = tid; x < 2048; x += 256) {                               \
                int r_ = x >> 3, c_ = x & 7;                                      \
                uint32_t off = (uint32_t)(r_ * 128 + c_ * 16);                    \
                off ^= (off >> 3) & 0x70;                                         \
                cpasync16(base_ + 16384 + off, Bk + (size_t)r_ * DIM + c_ * 16);  \
            }                                                                     \
            CP_COMMIT();                                                          \
        } while (0)

    LOAD_STAGE(0, 0);
    LOAD_STAGE(1, 1);

    #pragma unroll 1
    for (int s = 0; s < 8; s++) {
        int slot = s & 1;
        if (s < 7) CP_WAIT(1); else CP_WAIT(0);
        __syncthreads();

        uint32_t sa = smem_base + slot * STAGE_BYTES;
        uint32_t sb = sa + 16384;

        #pragma unroll
        for (int kk = 0; kk < 4; kk++) {
            uint32_t af[4][4];
            #pragma unroll
            for (int mi = 0; mi < 4; mi++) {
                int r = wr * 64 + mi * 16 + (lane & 7) + ((lane >> 3) & 1) * 8;
                int cb = kk * 32 + ((lane >> 4) & 1) * 16;
                uint32_t off = (uint32_t)(r * 128 + cb);
                off ^= (off >> 3) & 0x70;
                LDMX4(af[mi], sa + off);
            }
            uint32_t bf[8][2];
            #pragma unroll
            for (int p = 0; p < 4; p++) {
                int r = wc * 64 + p * 16 + ((lane >> 4) & 1) * 8 + (lane & 7);
                int cb = kk * 32 + ((lane >> 3) & 1) * 16;
                uint32_t off = (uint32_t)(r * 128 + cb);
                off ^= (off >> 3) & 0x70;
                uint32_t t[4];
                LDMX4(t, sb + off);
                bf[2 * p + 0][0] = t[0]; bf[2 * p + 0][1] = t[1];
                bf[2 * p + 1][0] = t[2]; bf[2 * p + 1][1] = t[3];
            }
            #pragma unroll
            for (int mi = 0; mi < 4; mi++)
                #pragma unroll
                for (int ni = 0; ni < 8; ni++)
                    mma16832h(acc[mi][ni], af[mi], bf[ni]);
        }

        if (s + 2 < 8) {
            __syncthreads();
            LOAD_STAGE(s + 2, slot);
        }
    }
    __syncthreads();   // buffers dead; reuse smem for sq staging

    float* sqi_sh = (float*)dsm;          // 128 floats
    float* sqj_sh = (float*)dsm + 128;    // 256 floats
    if (tid < 128) sqi_sh[tid] = g_sq[ti * 128 + tid];
    sqj_sh[tid] = g_sq[cs + tid];
    __syncthreads();

    // epilogue: acc holds 256 * dot (f16). 2*dot = acc/128.
    float local = 0.f;
    int r0 = lane >> 2, c0 = (lane & 3) * 2;
    #pragma unroll
    for (int mi = 0; mi < 4; mi++) {
        float si0 = sqi_sh[wr * 64 + mi * 16 + r0];
        float si1 = sqi_sh[wr * 64 + mi * 16 + r0 + 8];
        int gi0 = ti * 128 + wr * 64 + mi * 16 + r0;
        #pragma unroll
        for (int ni = 0; ni < 8; ni++) {
            int jl = wc * 64 + ni * 8 + c0;
            float sj0 = sqj_sh[jl], sj1 = sqj_sh[jl + 1];
            int gj0 = cs + jl;
            float2 lo = __half22float2(*(const __half2*)&acc[mi][ni][0]); // (r0,c0),(r0,c0+1)
            float2 hi = __half22float2(*(const __half2*)&acc[mi][ni][1]); // (r0+8,c0),(r0+8,c0+1)
            float dots[4] = {lo.x, lo.y, hi.x, hi.y};
            #pragma unroll
            for (int e = 0; e < 4; e++) {
                float si = (e >> 1) ? si1 : si0;
                float sj = (e & 1) ? sj1 : sj0;
                int gi = gi0 + ((e >> 1) ? 8 : 0);
                int gj = gj0 + (e & 1);
                float d2 = fmaxf(si + sj - dots[e] * (1.f / 128.f), 0.f);
                if (gj > gi) local += 2.f * __expf(-0.5f * d2);
            }
        }
    }

    #pragma unroll
    for (int o = 16; o; o >>= 1) local += __shfl_xor_sync(0xFFFFFFFFu, local, o);
    __shared__ float part[8];
    if (lane == 0) part[warp] = local;
    __syncthreads();
    if (tid == 0) {
        float tot = 0.f;
        #pragma unroll
        for (int i = 0; i < 8; i++) tot += part[i];
        g_negpart[blockIdx.x] = tot;
    }
}

// -------------------------------------------------------------------------
// Kernel 3: deterministic finalize
// -------------------------------------------------------------------------
__global__ __launch_bounds__(256) void finalize_kernel(float* out) {
    __shared__ double sh[256];
    int tid = threadIdx.x;

    double p = 0.0;
    for (int i = tid; i < NR; i += 256) p += (double)g_pos[i];
    sh[tid] = p;
    __syncthreads();
    for (int s = 128; s; s >>= 1) {
        if (tid < s) sh[tid] += sh[tid + s];
        __syncthreads();
    }
    double pos_sum = sh[0];
    __syncthreads();

    double n = 0.0;
    for (int i = tid; i < NBLK; i += 256) n += (double)g_negpart[i];
    sh[tid] = n;
    __syncthreads();
    for (int s = 128; s; s >>= 1) {
        if (tid < s) sh[tid] += sh[tid + s];
        __syncthreads();
    }
    if (tid == 0) {
        double star_mean = sh[0] / ((double)NR * (double)(NR - 1)) + 1e-8;
        double loss = -(pos_sum / (double)NR) + 64.0 * star_mean;
        out[0] = (float)loss;
    }
}

extern "C" void kernel_launch(void* const* d_in, const int* in_sizes, int n_in,
                              void* d_out, int out_size) {
    const float* z = (const float*)d_in[0];
    float* out = (float*)d_out;
    cudaFuncSetAttribute(gram_kernel, cudaFuncAttributeMaxDynamicSharedMemorySize,
                         SMEM_TOTAL);
    normalize_kernel<<<1024, 128>>>(z);
    gram_kernel<<<NBLK, 256, SMEM_TOTAL>>>();
    finalize_kernel<<<1, 256>>>(out);
}

// round 6
// speedup vs baseline: 2.2045x; 1.0749x over previous
#include <cuda_runtime.h>
#include <cuda_bf16.h>
#include <stdint.h>

// Problem constants
#define NR 4096
#define DIM 1024                 // bytes/row in fp8
#define NT 32                    // 128-row tiles per dim
#define NBLK 528                 // upper-tri 128x128 tiles
#define BKB 64                   // K bytes per stage
#define NSTG 16                  // 1024 / 64
#define STAGE_BYTES 16384        // A 128x64B + B 128x64B
#define SMEM_TOTAL (3 * STAGE_BYTES)   // 48KB, 3-stage ring -> 2 CTAs/SM

// Scratch (static device globals; no runtime allocation)
__device__ uint8_t g_zq[NR * DIM];   // normalized z1 * 16, e4m3 (4 MB, L2-resident)
__device__ float g_sq[NR];
__device__ float g_pos[NR];
__device__ float g_negpart[NBLK];

__device__ __forceinline__ uint32_t su32(const void* p) {
    return (uint32_t)__cvta_generic_to_shared(p);
}
__device__ __forceinline__ void cpasync16(uint32_t dst, const void* g) {
    asm volatile("cp.async.cg.shared.global [%0], [%1], 16;" :: "r"(dst), "l"(g));
}
#define CP_COMMIT() asm volatile("cp.async.commit_group;")
#define CP_WAIT(n)  asm volatile("cp.async.wait_group %0;" :: "n"(n))

#define LDMX4(R, addr) \
    asm volatile("ldmatrix.sync.aligned.m8n8.x4.shared.b16 {%0,%1,%2,%3}, [%4];" \
                 : "=r"((R)[0]), "=r"((R)[1]), "=r"((R)[2]), "=r"((R)[3]) : "r"(addr))

__device__ __forceinline__ void mma16832(float* c, const uint32_t* a, const uint32_t* b) {
    asm volatile(
        "mma.sync.aligned.m16n8k32.row.col.f32.e4m3.e4m3.f32 "
        "{%0,%1,%2,%3}, {%4,%5,%6,%7}, {%8,%9}, {%0,%1,%2,%3};"
        : "+f"(c[0]), "+f"(c[1]), "+f"(c[2]), "+f"(c[3])
        : "r"(a[0]), "r"(a[1]), "r"(a[2]), "r"(a[3]), "r"(b[0]), "r"(b[1]));
}

__device__ __forceinline__ uint32_t pack4_e4m3(float v0, float v1, float v2, float v3) {
    uint16_t h01, h23;
    asm("cvt.rn.satfinite.e4m3x2.f32 %0, %1, %2;" : "=h"(h01) : "f"(v1), "f"(v0));
    asm("cvt.rn.satfinite.e4m3x2.f32 %0, %1, %2;" : "=h"(h23) : "f"(v3), "f"(v2));
    return (uint32_t)h01 | ((uint32_t)h23 << 16);
}

// SW64 swizzle for 64B-wide rows (conflict-free ldmatrix over 8 rows)
__device__ __forceinline__ uint32_t sw64(uint32_t off) {
    return off ^ ((off >> 3) & 0x30);
}

// -------------------------------------------------------------------------
// Kernel 1: block-per-row normalize. 4096 blocks x 128 thr for full
// occupancy (16k warps). Emits e4m3 (z * 16).
// -------------------------------------------------------------------------
__global__ __launch_bounds__(128) void normalize_kernel(const float* __restrict__ z) {
    int row = blockIdx.x, tid = threadIdx.x;
    int warp = tid >> 5, lane = tid & 31;

    const float4* z1p = (const float4*)(z + (size_t)row * DIM);
    const float4* z2p = (const float4*)(z + (size_t)(row + NR) * DIM);

    float4 a0 = z1p[tid], a1 = z1p[tid + 128];
    float4 b0 = z2p[tid], b1 = z2p[tid + 128];

    float s1 = a0.x*a0.x + a0.y*a0.y + a0.z*a0.z + a0.w*a0.w
             + a1.x*a1.x + a1.y*a1.y + a1.z*a1.z + a1.w*a1.w;
    float s2 = b0.x*b0.x + b0.y*b0.y + b0.z*b0.z + b0.w*b0.w
             + b1.x*b1.x + b1.y*b1.y + b1.z*b1.z + b1.w*b1.w;
    float s12 = a0.x*b0.x + a0.y*b0.y + a0.z*b0.z + a0.w*b0.w
              + a1.x*b1.x + a1.y*b1.y + a1.z*b1.z + a1.w*b1.w;

    #pragma unroll
    for (int o = 16; o; o >>= 1) {
        s1  += __shfl_xor_sync(0xFFFFFFFFu, s1, o);
        s2  += __shfl_xor_sync(0xFFFFFFFFu, s2, o);
        s12 += __shfl_xor_sync(0xFFFFFFFFu, s12, o);
    }
    __shared__ float sh[4][3];
    if (lane == 0) { sh[warp][0] = s1; sh[warp][1] = s2; sh[warp][2] = s12; }
    __syncthreads();
    s1 = sh[0][0] + sh[1][0] + sh[2][0] + sh[3][0];
    s2 = sh[0][1] + sh[1][1] + sh[2][1] + sh[3][1];
    s12 = sh[0][2] + sh[1][2] + sh[2][2] + sh[3][2];

    float inv1 = 1.f / fmaxf(sqrtf(s1), 1e-12f);
    float inv2 = 1.f / fmaxf(sqrtf(s2), 1e-12f);
    float q1 = 16.f * inv1;

    uint32_t* dst = (uint32_t*)(g_zq + (size_t)row * DIM);
    dst[tid]       = pack4_e4m3(a0.x * q1, a0.y * q1, a0.z * q1, a0.w * q1);
    dst[tid + 128] = pack4_e4m3(a1.x * q1, a1.y * q1, a1.z * q1, a1.w * q1);

    if (tid == 0) {
        float n1sq = s1 * inv1 * inv1;
        float n2sq = s2 * inv2 * inv2;
        float dp = n1sq + n2sq - 2.f * s12 * inv1 * inv2;
        g_pos[row] = logf(__expf(-0.5f * dp) + 1e-8f) + 1.f;
        g_sq[row] = n1sq;
    }
}

// -------------------------------------------------------------------------
// Kernel 2: fp8 Gram (mma.sync m16n8k32 e4m3 f32acc) + fused exp-reduce.
// 528 CTAs x 256 thr, 2 CTAs/SM (4 MMA-issuing warps per SMSP).
// CTA tile 128x128; warp tile 64x32. 16 K-stages of 64B, 3-stage ring.
// -------------------------------------------------------------------------
__global__ __launch_bounds__(256, 2) void gram_kernel() {
    __shared__ uint8_t dsm[SMEM_TOTAL];
    uint32_t smem_base = su32(dsm);
    int tid = threadIdx.x;
    int warp = tid >> 5, lane = tid & 31;
    int wr = warp >> 2, wc = warp & 3;   // warp grid 2 x 4 (rows x cols)

    // bid -> (ti, tj), tj >= ti
    int ti = 0, rem = blockIdx.x;
    #pragma unroll 1
    while (rem >= NT - ti) { rem -= NT - ti; ti++; }
    int tj = ti + rem;

    const uint8_t* Abase = g_zq + (size_t)ti * 128 * DIM;
    const uint8_t* Bbase = g_zq + (size_t)tj * 128 * DIM;

    float acc[4][4][4];
    #pragma unroll
    for (int i = 0; i < 4; i++)
        #pragma unroll
        for (int j = 0; j < 4; j++)
            #pragma unroll
            for (int e = 0; e < 4; e++) acc[i][j][e] = 0.f;

    // stage s covers K bytes [s*64, s*64+64). 1024 x 16B chunks / 256 thr.
    #define LOAD_STAGE(s, slot)                                                   \
        do {                                                                      \
            uint32_t base_ = smem_base + (slot) * STAGE_BYTES;                    \
            const uint8_t* Ak = Abase + (s) * BKB;                                \
            const uint8_t* Bk = Bbase + (s) * BKB;                                \
            _Pragma("unroll")                                                     \
            for (int x = tid; x < 512; x += 256) {                                \
                int r_ = x >> 2, c_ = x & 3;                                      \
                uint32_t off = sw64((uint32_t)(r_ * 64 + c_ * 16));               \
                cpasync16(base_ + off, Ak + (size_t)r_ * DIM + c_ * 16);          \
            }                                                                     \
            _Pragma("unroll")                                                     \
            for (int x = tid; x < 512; x += 256) {                                \
                int r_ = x >> 2, c_ = x & 3;                                      \
                uint32_t off = sw64((uint32_t)(r_ * 64 + c_ * 16));               \
                cpasync16(base_ + 8192 + off, Bk + (size_t)r_ * DIM + c_ * 16);   \
            }                                                                     \
            CP_COMMIT();                                                          \
        } while (0)

    LOAD_STAGE(0, 0);
    LOAD_STAGE(1, 1);
    LOAD_STAGE(2, 2);

    int slot = 0;
    #pragma unroll 1
    for (int s = 0; s < NSTG; s++) {
        if (s < NSTG - 3)      CP_WAIT(2);
        else if (s == NSTG - 3) CP_WAIT(2);
        else if (s == NSTG - 2) CP_WAIT(1);
        else                    CP_WAIT(0);
        __syncthreads();

        uint32_t sa = smem_base + slot * STAGE_BYTES;
        uint32_t sb = sa + 8192;

        #pragma unroll
        for (int kk = 0; kk < 2; kk++) {
            uint32_t af[4][4];
            #pragma unroll
            for (int mi = 0; mi < 4; mi++) {
                int r = wr * 64 + mi * 16 + (lane & 7) + ((lane >> 3) & 1) * 8;
                int cb = kk * 32 + ((lane >> 4) & 1) * 16;
                LDMX4(af[mi], sa + sw64((uint32_t)(r * 64 + cb)));
            }
            uint32_t bf[4][2];
            #pragma unroll
            for (int p = 0; p < 2; p++) {
                int r = wc * 32 + p * 16 + ((lane >> 4) & 1) * 8 + (lane & 7);
                int cb = kk * 32 + ((lane >> 3) & 1) * 16;
                uint32_t t[4];
                LDMX4(t, sb + sw64((uint32_t)(r * 64 + cb)));
                bf[2 * p + 0][0] = t[0]; bf[2 * p + 0][1] = t[1];
                bf[2 * p + 1][0] = t[2]; bf[2 * p + 1][1] = t[3];
            }
            #pragma unroll
            for (int mi = 0; mi < 4; mi++)
                #pragma unroll
                for (int ni = 0; ni < 4; ni++)
                    mma16832(acc[mi][ni], af[mi], bf[ni]);
        }

        if (s + 3 < NSTG) {
            __syncthreads();           // all warps done reading this slot
            LOAD_STAGE(s + 3, slot);
        }
        slot = (slot == 2) ? 0 : slot + 1;
    }
    __syncthreads();   // buffers dead; reuse smem for sq staging

    float* sqi_sh = (float*)dsm;          // 128 floats
    float* sqj_sh = (float*)dsm + 128;    // 128 floats
    if (tid < 128) sqi_sh[tid] = g_sq[ti * 128 + tid];
    else           sqj_sh[tid - 128] = g_sq[tj * 128 + (tid - 128)];
    __syncthreads();

    // epilogue: acc = 256 * dot; d2 = si + sj - acc/128.
    float local = 0.f;
    int r0 = lane >> 2, c0 = (lane & 3) * 2;
    #pragma unroll
    for (int mi = 0; mi < 4; mi++) {
        float si0 = sqi_sh[wr * 64 + mi * 16 + r0];
        float si1 = sqi_sh[wr * 64 + mi * 16 + r0 + 8];
        int gi0 = ti * 128 + wr * 64 + mi * 16 + r0;
        #pragma unroll
        for (int ni = 0; ni < 4; ni++) {
            int jl = wc * 32 + ni * 8 + c0;
            float sj0 = sqj_sh[jl], sj1 = sqj_sh[jl + 1];
            int gj0 = tj * 128 + jl;
            #pragma unroll
            for (int e = 0; e < 4; e++) {
                float si = (e >> 1) ? si1 : si0;
                float sj = (e & 1) ? sj1 : sj0;
                int gi = gi0 + ((e >> 1) ? 8 : 0);
                int gj = gj0 + (e & 1);
                float d2 = fmaxf(si + sj - acc[mi][ni][e] * (1.f / 128.f), 0.f);
                if (gj > gi) local += 2.f * __expf(-0.5f * d2);
            }
        }
    }

    #pragma unroll
    for (int o = 16; o; o >>= 1) local += __shfl_xor_sync(0xFFFFFFFFu, local, o);
    __shared__ float part[8];
    if (lane == 0) part[warp] = local;
    __syncthreads();
    if (tid == 0) {
        float tot = 0.f;
        #pragma unroll
        for (int i = 0; i < 8; i++) tot += part[i];
        g_negpart[blockIdx.x] = tot;
    }
}

// -------------------------------------------------------------------------
// Kernel 3: deterministic finalize
// -------------------------------------------------------------------------
__global__ __launch_bounds__(256) void finalize_kernel(float* out) {
    __shared__ double sh[256];
    int tid = threadIdx.x;

    double p = 0.0;
    for (int i = tid; i < NR; i += 256) p += (double)g_pos[i];
    sh[tid] = p;
    __syncthreads();
    for (int s = 128; s; s >>= 1) {
        if (tid < s) sh[tid] += sh[tid + s];
        __syncthreads();
    }
    double pos_sum = sh[0];
    __syncthreads();

    double n = 0.0;
    for (int i = tid; i < NBLK; i += 256) n += (double)g_negpart[i];
    sh[tid] = n;
    __syncthreads();
    for (int s = 128; s; s >>= 1) {
        if (tid < s) sh[tid] += sh[tid + s];
        __syncthreads();
    }
    if (tid == 0) {
        double star_mean = sh[0] / ((double)NR * (double)(NR - 1)) + 1e-8;
        double loss = -(pos_sum / (double)NR) + 64.0 * star_mean;
        out[0] = (float)loss;
    }
}

extern "C" void kernel_launch(void* const* d_in, const int* in_sizes, int n_in,
                              void* d_out, int out_size) {
    const float* z = (const float*)d_in[0];
    float* out = (float*)d_out;
    normalize_kernel<<<NR, 128>>>(z);
    gram_kernel<<<NBLK, 256>>>();
    finalize_kernel<<<1, 256>>>(out);
}